// round 8
// baseline (speedup 1.0000x reference)
#include <cuda_runtime.h>
#include <cuda_bf16.h>

// Fixed shapes from reference setup_inputs
#define NPTS 8192
#define TPB  256
#define TILE 512                     // i-tile edge (TPB * 2 i-points per thread)
#define JC   128                     // j-chunk per CTA
#define NTILES (NPTS / TILE)         // 16
#define NTRI (NTILES * (NTILES + 1) / 2)   // 136 triangular tiles
#define NBLK (NTRI * 4)              // 544 CTAs

// Sorted copies + metadata (no device allocation; fixed globals)
__device__ float g_sx[NPTS], g_sy[NPTS], g_sz[NPTS], g_ss[NPTS];
__device__ float g_q0[NPTS], g_q1[NPTS], g_q2[NPTS], g_q3[NPTS];
__device__ unsigned int g_code[NPTS];
__device__ int g_rank[NPTS];
__device__ float g_partials[NBLK];
__device__ unsigned int g_count;     // zero at load; self-reset each launch

// A&S 7.1.25 (3-term, |eps| <= 2.5e-5), x = r/sqrt(2) folded into p
#define P3S  0.3326701f              // 0.47047 / sqrt(2)
#define A1c  0.3480242f
#define A2c  (-0.0958798f)
#define A3c  0.7478556f
#define NEG_HALF_LOG2E (-0.7213475204444817f)
#define SELF_RATIO 0.7978845608028654f   // (1/(2pi)^1.5) / (1/(4pi))
#define NEAR_R2 16.0f                // erfc(sqrt(8)) ~ 7e-5 -> far field = 1/r

__device__ __forceinline__ float rsqf(float a) {
    float r; asm("rsqrt.approx.f32 %0,%1;" : "=f"(r) : "f"(a)); return r;
}
__device__ __forceinline__ float rcpf(float a) {
    float r; asm("rcp.approx.f32 %0,%1;" : "=f"(r) : "f"(a)); return r;
}
__device__ __forceinline__ float exf(float a) {
    float r; asm("ex2.approx.f32 %0,%1;" : "=f"(r) : "f"(a)); return r;
}

// Full near-field kernel value erf(r/sqrt2)/r given r2 and rv = rsqrt(r2).
__device__ __forceinline__ float kern_corr(float r2, float rv) {
    const float r  = r2 * rv;
    const float tt = rcpf(fmaf(P3S, r, 1.0f));       // MUFU.RCP
    float h = fmaf(A3c, tt, A2c);
    h = fmaf(h, tt, A1c);
    const float u = (h * tt) * exf(r2 * NEG_HALF_LOG2E);  // MUFU.EX2
    return fmaf(-u, rv, rv);                         // (1 - poly*exp) * rv
}

// ---------- Pre-pass A: Morton codes + rank reset ----------
__device__ __forceinline__ unsigned expand10(unsigned v) {
    v &= 0x3FFu;
    v = (v | (v << 16)) & 0x030000FFu;
    v = (v | (v <<  8)) & 0x0300F00Fu;
    v = (v | (v <<  4)) & 0x030C30C3u;
    v = (v | (v <<  2)) & 0x09249249u;
    return v;
}
__global__ void morton_kernel(const float* __restrict__ pos) {
    const int i = blockIdx.x * blockDim.x + threadIdx.x;
    const float x = pos[3 * i + 0];
    const float y = pos[3 * i + 1];
    const float z = pos[3 * i + 2];
    const unsigned ux = (unsigned)fminf(fmaxf((x + 25.f) * 20.47f, 0.f), 1023.f);
    const unsigned uy = (unsigned)fminf(fmaxf((y + 25.f) * 20.47f, 0.f), 1023.f);
    const unsigned uz = (unsigned)fminf(fmaxf((z + 25.f) * 20.47f, 0.f), 1023.f);
    g_code[i] = (expand10(ux) << 2) | (expand10(uy) << 1) | expand10(uz);
    g_rank[i] = 0;
    if (i == 0) g_count = 0;   // belt & braces for replay
}

// ---------- Pre-pass B: rank by counting (deterministic: int atomics) ----------
__global__ void rank_kernel() {
    __shared__ unsigned sc[1024];
    const int t = threadIdx.x;
    const int jbase = blockIdx.y * 1024;
    for (int u = t; u < 1024; u += TPB) sc[u] = g_code[jbase + u];
    __syncthreads();
    const int i = blockIdx.x * TPB + t;
    const unsigned ci = g_code[i];
    int cnt = 0;
#pragma unroll 8
    for (int j = 0; j < 1024; j++) {
        const unsigned cj = sc[j];
        cnt += (cj < ci) || (cj == ci && (jbase + j) < i);   // stable tiebreak
    }
    atomicAdd(&g_rank[i], cnt);
}

// ---------- Pre-pass C: gather into sorted SoA ----------
__global__ void gather_kernel(const float* __restrict__ pos, const float* __restrict__ q) {
    const int i = blockIdx.x * blockDim.x + threadIdx.x;
    const int r = g_rank[i];
    const float x = pos[3 * i + 0];
    const float y = pos[3 * i + 1];
    const float z = pos[3 * i + 2];
    g_sx[r] = x; g_sy[r] = y; g_sz[r] = z;
    g_ss[r] = fmaf(x, x, fmaf(y, y, z * z));
    g_q0[r] = q[4 * i + 0];
    g_q1[r] = q[4 * i + 1];
    g_q2[r] = q[4 * i + 2];
    g_q3[r] = q[4 * i + 3];
}

// ---------- Main pair kernel (sorted data, far-field vote-skip) ----------
__global__ void __launch_bounds__(TPB, 4)
ewald_pair_kernel(float* __restrict__ out) {
    __shared__ float4 sp[JC];   // {x, y, z, |p|^2}
    __shared__ float4 sb[JC];   // {b0, b1, b2, b3}

    const int t = threadIdx.x;
    const int tile  = blockIdx.x >> 2;
    const int chunk = blockIdx.x & 3;
    int I = 0, rem = tile;
    while (rem >= NTILES - I) { rem -= NTILES - I; I++; }
    const int J = I + rem;
    const bool diag = (I == J);

    const int jbase = J * TILE + chunk * JC;
    if (t < JC) {
        const int j = jbase + t;
        sp[t] = make_float4(g_sx[j], g_sy[j], g_sz[j], g_ss[j]);
    } else {
        const int tq = t - JC, j = jbase + tq;
        sb[tq] = make_float4(g_q0[j], g_q1[j], g_q2[j], g_q3[j]);
    }
    __syncthreads();

    const int i0 = I * TILE + 2 * t;
    const float x0 = g_sx[i0], x1 = g_sx[i0 + 1];
    const float y0 = g_sy[i0], y1 = g_sy[i0 + 1];
    const float z0 = g_sz[i0], z1 = g_sz[i0 + 1];

    float acc0l = 0.f, acc1l = 0.f, acc2l = 0.f, acc3l = 0.f;
    float acc0h = 0.f, acc1h = 0.f, acc2h = 0.f, acc3h = 0.f;

    if (!diag) {
        // dot-form r^2 = (si + sj) - 2 pi.pj
        const float nx2l = -2.f * x0, nx2h = -2.f * x1;
        const float ny2l = -2.f * y0, ny2h = -2.f * y1;
        const float nz2l = -2.f * z0, nz2h = -2.f * z1;
        const float sil = g_ss[i0], sih = g_ss[i0 + 1];
#pragma unroll 8
        for (int jj = 0; jj < JC; jj++) {
            const float4 p = sp[jj];
            const float r2l = fmaf(p.x, nx2l, fmaf(p.y, ny2l, fmaf(p.z, nz2l, p.w + sil)));
            const float r2h = fmaf(p.x, nx2h, fmaf(p.y, ny2h, fmaf(p.z, nz2h, p.w + sih)));
            const float rvl = rsqf(r2l);
            const float rvh = rsqf(r2h);
            float kl = rvl, kh = rvh;                  // far-field: erf == 1
            if (__any_sync(0xffffffffu, fminf(r2l, r2h) < NEAR_R2)) {
                kl = kern_corr(r2l, rvl);              // full path reproduces
                kh = kern_corr(r2h, rvh);              // far value too (u ~ 0)
            }
            const float4 b = sb[jj];
            acc0l = fmaf(kl, b.x, acc0l); acc0h = fmaf(kh, b.x, acc0h);
            acc1l = fmaf(kl, b.y, acc1l); acc1h = fmaf(kh, b.y, acc1h);
            acc2l = fmaf(kl, b.z, acc2l); acc2h = fmaf(kh, b.z, acc2h);
            acc3l = fmaf(kl, b.w, acc3l); acc3h = fmaf(kh, b.w, acc3h);
        }
    } else {
        // exact diff-form r^2 so the diagonal is exactly zero for the select
        const float nxl = -x0, nxh = -x1;
        const float nyl = -y0, nyh = -y1;
        const float nzl = -z0, nzh = -z1;
#pragma unroll 8
        for (int jj = 0; jj < JC; jj++) {
            const float4 p = sp[jj];
            const float dxl = p.x + nxl, dxh = p.x + nxh;
            const float dyl = p.y + nyl, dyh = p.y + nyh;
            const float dzl = p.z + nzl, dzh = p.z + nzh;
            const float r2l = fmaf(dxl, dxl, fmaf(dyl, dyl, dzl * dzl));
            const float r2h = fmaf(dxh, dxh, fmaf(dyh, dyh, dzh * dzh));
            const float rvl = rsqf(r2l);
            const float rvh = rsqf(r2h);
            float kl = rvl, kh = rvh;
            if (__any_sync(0xffffffffu, fminf(r2l, r2h) < NEAR_R2)) {
                kl = kern_corr(r2l, rvl);
                kh = kern_corr(r2h, rvh);
            }
            kl = (r2l > 0.f) ? kl : 0.f;               // exact-zero diagonal
            kh = (r2h > 0.f) ? kh : 0.f;
            const float4 b = sb[jj];
            acc0l = fmaf(kl, b.x, acc0l); acc0h = fmaf(kh, b.x, acc0h);
            acc1l = fmaf(kl, b.y, acc1l); acc1h = fmaf(kh, b.y, acc1h);
            acc2l = fmaf(kl, b.z, acc2l); acc2h = fmaf(kh, b.z, acc2h);
            acc3l = fmaf(kl, b.w, acc3l); acc3h = fmaf(kh, b.w, acc3h);
        }
    }

    // dot with i charges (L1/L2 hit)
    const float a0l = g_q0[i0], a0h = g_q0[i0 + 1];
    const float a1l = g_q1[i0], a1h = g_q1[i0 + 1];
    const float a2l = g_q2[i0], a2h = g_q2[i0 + 1];
    const float a3l = g_q3[i0], a3h = g_q3[i0 + 1];
    float s = fmaf(a0l, acc0l, fmaf(a1l, acc1l, fmaf(a2l, acc2l, a3l * acc3l)))
            + fmaf(a0h, acc0h, fmaf(a1h, acc1h, fmaf(a2h, acc2h, a3h * acc3h)));
    if (!diag) s = s + s;
    else if (chunk == 0) {
        const float qq = fmaf(a0l, a0l, fmaf(a1l, a1l, fmaf(a2l, a2l, a3l * a3l)))
                       + fmaf(a0h, a0h, fmaf(a1h, a1h, fmaf(a2h, a2h, a3h * a3h)));
        s = fmaf(SELF_RATIO, qq, s);
    }

    // deterministic in-block reduction (8 warps)
#pragma unroll
    for (int o = 16; o > 0; o >>= 1)
        s += __shfl_down_sync(0xffffffffu, s, o);

    __shared__ float red[TPB / 32];
    if ((t & 31) == 0) red[t >> 5] = s;
    __syncthreads();

    __shared__ bool is_last;
    if (t == 0) {
        g_partials[blockIdx.x] = ((red[0] + red[1]) + (red[2] + red[3]))
                               + ((red[4] + red[5]) + (red[6] + red[7]));
        __threadfence();
        const unsigned int c = atomicAdd(&g_count, 1u);
        is_last = (c == NBLK - 1);
    }
    __syncthreads();

    if (is_last) {
        __threadfence();
        double d = (double)g_partials[t] + (double)g_partials[t + 256];
        if (t < NBLK - 512) d += (double)g_partials[t + 512];

        __shared__ double rs[TPB];
        rs[t] = d;
        __syncthreads();
#pragma unroll
        for (int o = TPB / 2; o > 0; o >>= 1) {
            if (t < o) rs[t] += rs[t + o];
            __syncthreads();
        }
        if (t == 0) {
            const double INV_4PI = 0.07957747154594767;
            out[0] = (float)(rs[0] * INV_4PI);
            g_count = 0;   // reset for next graph replay
        }
    }
}

extern "C" void kernel_launch(void* const* d_in, const int* in_sizes, int n_in,
                              void* d_out, int out_size) {
    const float* pos = (const float*)d_in[0];   // [8192,3] fp32
    const float* q   = (const float*)d_in[1];   // [8192,4] fp32
    float* out = (float*)d_out;                 // [1] fp32

    morton_kernel<<<NPTS / 256, 256>>>(pos);
    rank_kernel<<<dim3(NPTS / 256, NPTS / 1024), 256>>>();
    gather_kernel<<<NPTS / 256, 256>>>(pos, q);
    ewald_pair_kernel<<<NBLK, TPB>>>(out);
}

// round 9
// speedup vs baseline: 1.2590x; 1.2590x over previous
#include <cuda_runtime.h>
#include <cuda_bf16.h>

// Fixed shapes from reference setup_inputs
#define NPTS 8192
#define TPB  256
#define TILE 256                     // i-tile edge (TPB * 1 i per thread)
#define JC   128                     // j-chunk per CTA
#define NTILES (NPTS / TILE)         // 32
#define NTRI (NTILES * (NTILES + 1) / 2)   // 528 triangular tiles
#define NBLK (NTRI * 2)              // 1056 CTAs (2 j-chunks per tile)

#define NBINS 4096                   // 12-bit Morton (4 bits/axis)
#define NSB   32                     // superblocks of 256 points

// Sorted copies + metadata (no device allocation; fixed globals)
__device__ float g_sx[NPTS], g_sy[NPTS], g_sz[NPTS], g_ss[NPTS];
__device__ float g_q0[NPTS], g_q1[NPTS], g_q2[NPTS], g_q3[NPTS];
__device__ unsigned g_bin[NPTS];
__device__ unsigned g_bh[NSB * NBINS];      // per-superblock histograms (self-cleaning)
__device__ unsigned g_tot[NBINS];
__device__ unsigned g_binstart[NBINS];
__device__ unsigned g_bstart[NSB * NBINS];
__device__ float g_partials[NBLK];
__device__ unsigned int g_count;            // zero at load; self-reset each launch

// A&S 7.1.25 (3-term, |eps| <= 2.5e-5), x = r/sqrt(2) folded into p
#define P3S  0.3326701f              // 0.47047 / sqrt(2)
#define A1c  0.3480242f
#define A2c  (-0.0958798f)
#define A3c  0.7478556f
#define NEG_HALF_LOG2E (-0.7213475204444817f)
#define SELF_RATIO 0.7978845608028654f   // (1/(2pi)^1.5) / (1/(4pi))
#define NEAR_R2 10.24f               // r=3.2: erfc(2.26)~1.4e-3, incoherent -> safe

__device__ __forceinline__ float rsqf(float a) {
    float r; asm("rsqrt.approx.f32 %0,%1;" : "=f"(r) : "f"(a)); return r;
}
__device__ __forceinline__ float rcpf(float a) {
    float r; asm("rcp.approx.f32 %0,%1;" : "=f"(r) : "f"(a)); return r;
}
__device__ __forceinline__ float exf(float a) {
    float r; asm("ex2.approx.f32 %0,%1;" : "=f"(r) : "f"(a)); return r;
}
// Near-field kernel value erf(r/sqrt2)/r given r2 and rv = rsqrt(r2).
__device__ __forceinline__ float kern_corr(float r2, float rv) {
    const float r  = r2 * rv;
    const float tt = rcpf(fmaf(P3S, r, 1.0f));            // MUFU.RCP
    float h = fmaf(A3c, tt, A2c);
    h = fmaf(h, tt, A1c);
    const float u = (h * tt) * exf(r2 * NEG_HALF_LOG2E);  // MUFU.EX2
    return fmaf(-u, rv, rv);                              // (1 - poly*exp) * rv
}

// ---------- K1: Morton bin + per-superblock histogram ----------
__device__ __forceinline__ unsigned spread4(unsigned v) {
    // 4 bits -> bits {0,3,6,9}
    return (v & 1u) | ((v & 2u) << 2) | ((v & 4u) << 4) | ((v & 8u) << 6);
}
__global__ void bin_hist_kernel(const float* __restrict__ pos) {
    const int i = blockIdx.x * blockDim.x + threadIdx.x;
    const float x = pos[3 * i + 0];
    const float y = pos[3 * i + 1];
    const float z = pos[3 * i + 2];
    const unsigned ux = (unsigned)fminf(fmaxf((x + 20.f) * 0.4f, 0.f), 15.f);
    const unsigned uy = (unsigned)fminf(fmaxf((y + 20.f) * 0.4f, 0.f), 15.f);
    const unsigned uz = (unsigned)fminf(fmaxf((z + 20.f) * 0.4f, 0.f), 15.f);
    const unsigned b = (spread4(ux) << 2) | (spread4(uy) << 1) | spread4(uz);
    g_bin[i] = b;
    atomicAdd(&g_bh[(i >> 8) * NBINS + b], 1u);   // counts: order-independent
}

// ---------- K2: bin totals (parallel over bins) ----------
__global__ void tot_kernel() {
    const int b = blockIdx.x * blockDim.x + threadIdx.x;
    unsigned s = 0;
#pragma unroll
    for (int m = 0; m < NSB; m++) s += g_bh[m * NBINS + b];
    g_tot[b] = s;
}

// ---------- K3: exclusive scan of bin totals (one CTA) ----------
__global__ void scan_kernel() {
    const int t = threadIdx.x;           // 256 threads, 16 bins each
    unsigned loc[16];
    unsigned s = 0;
#pragma unroll
    for (int k = 0; k < 16; k++) { loc[k] = s; s += g_tot[t * 16 + k]; }
    __shared__ unsigned ts[256];
    ts[t] = s;
    __syncthreads();
    if (t == 0) {                        // tiny serial scan of 256 sums
        unsigned run = 0;
        for (int u = 0; u < 256; u++) { unsigned v = ts[u]; ts[u] = run; run += v; }
    }
    __syncthreads();
    const unsigned base = ts[t];
#pragma unroll
    for (int k = 0; k < 16; k++) g_binstart[t * 16 + k] = base + loc[k];
}

// ---------- K4: per-(superblock,bin) column starts; self-clean g_bh ----------
__global__ void colstart_kernel() {
    const int b = blockIdx.x * blockDim.x + threadIdx.x;
    unsigned run = g_binstart[b];
#pragma unroll
    for (int m = 0; m < NSB; m++) {
        const unsigned c = g_bh[m * NBINS + b];
        g_bstart[m * NBINS + b] = run;
        run += c;
        g_bh[m * NBINS + b] = 0;         // clean for next graph replay
    }
}

// ---------- K5: stable rank + gather into sorted SoA ----------
__global__ void gather_kernel(const float* __restrict__ pos, const float* __restrict__ q) {
    __shared__ unsigned sbin[256];
    const int t = threadIdx.x;
    const int i = blockIdx.x * 256 + t;
    const unsigned b = g_bin[i];
    sbin[t] = b;
    __syncthreads();
    unsigned off = 0;
#pragma unroll 8
    for (int j = 0; j < 256; j++)
        off += (sbin[j] == b) && (j < t);          // stable within superblock
    const unsigned r = g_bstart[blockIdx.x * NBINS + b] + off;
    const float x = pos[3 * i + 0];
    const float y = pos[3 * i + 1];
    const float z = pos[3 * i + 2];
    g_sx[r] = x; g_sy[r] = y; g_sz[r] = z;
    g_ss[r] = fmaf(x, x, fmaf(y, y, z * z));
    g_q0[r] = q[4 * i + 0];
    g_q1[r] = q[4 * i + 1];
    g_q2[r] = q[4 * i + 2];
    g_q3[r] = q[4 * i + 3];
}

// ---------- Main pair kernel (sorted data, far-field vote-skip) ----------
__global__ void __launch_bounds__(TPB, 4)
ewald_pair_kernel(float* __restrict__ out) {
    __shared__ float4 sp[JC];   // {x, y, z, |p|^2}
    __shared__ float4 sb[JC];   // {b0, b1, b2, b3}

    const int t = threadIdx.x;
    const int tile  = blockIdx.x >> 1;
    const int chunk = blockIdx.x & 1;
    int I = 0, rem = tile;
    while (rem >= NTILES - I) { rem -= NTILES - I; I++; }
    const int J = I + rem;
    const bool diag = (I == J);

    const int jbase = J * TILE + chunk * JC;
    if (t < JC) {
        const int j = jbase + t;
        sp[t] = make_float4(g_sx[j], g_sy[j], g_sz[j], g_ss[j]);
    } else {
        const int tq = t - JC, j = jbase + tq;
        sb[tq] = make_float4(g_q0[j], g_q1[j], g_q2[j], g_q3[j]);
    }
    __syncthreads();

    const int i0 = I * TILE + t;           // one i per thread (small warp blob)
    const float xi = g_sx[i0], yi = g_sy[i0], zi = g_sz[i0];

    float acc0 = 0.f, acc1 = 0.f, acc2 = 0.f, acc3 = 0.f;

    if (!diag) {
        // dot-form r^2 = (si + sj) - 2 pi.pj
        const float nx2 = -2.f * xi, ny2 = -2.f * yi, nz2 = -2.f * zi;
        const float si  = g_ss[i0];
#pragma unroll 8
        for (int jj = 0; jj < JC; jj++) {
            const float4 p = sp[jj];
            const float r2 = fmaf(p.x, nx2, fmaf(p.y, ny2, fmaf(p.z, nz2, p.w + si)));
            const float rv = rsqf(r2);
            float k = rv;                                   // far field: erf == 1
            if (__any_sync(0xffffffffu, r2 < NEAR_R2))
                k = kern_corr(r2, rv);                      // also valid when far
            const float4 b = sb[jj];
            acc0 = fmaf(k, b.x, acc0);
            acc1 = fmaf(k, b.y, acc1);
            acc2 = fmaf(k, b.z, acc2);
            acc3 = fmaf(k, b.w, acc3);
        }
    } else {
        // exact diff-form r^2 so the diagonal is exactly zero for the select
#pragma unroll 8
        for (int jj = 0; jj < JC; jj++) {
            const float4 p = sp[jj];
            const float dx = p.x - xi;
            const float dy = p.y - yi;
            const float dz = p.z - zi;
            const float r2 = fmaf(dx, dx, fmaf(dy, dy, dz * dz));
            const float rv = rsqf(r2);
            float k = rv;
            if (__any_sync(0xffffffffu, r2 < NEAR_R2))
                k = kern_corr(r2, rv);
            k = (r2 > 0.f) ? k : 0.f;                       // exact-zero diagonal
            const float4 b = sb[jj];
            acc0 = fmaf(k, b.x, acc0);
            acc1 = fmaf(k, b.y, acc1);
            acc2 = fmaf(k, b.z, acc2);
            acc3 = fmaf(k, b.w, acc3);
        }
    }

    // dot with i charges (L1/L2 hit)
    const float a0 = g_q0[i0], a1 = g_q1[i0], a2 = g_q2[i0], a3 = g_q3[i0];
    float s = fmaf(a0, acc0, fmaf(a1, acc1, fmaf(a2, acc2, a3 * acc3)));
    if (!diag) s = s + s;
    else if (chunk == 0) {
        const float qq = fmaf(a0, a0, fmaf(a1, a1, fmaf(a2, a2, a3 * a3)));
        s = fmaf(SELF_RATIO, qq, s);
    }

    // deterministic in-block reduction (8 warps)
#pragma unroll
    for (int o = 16; o > 0; o >>= 1)
        s += __shfl_down_sync(0xffffffffu, s, o);

    __shared__ float red[TPB / 32];
    if ((t & 31) == 0) red[t >> 5] = s;
    __syncthreads();

    __shared__ bool is_last;
    if (t == 0) {
        g_partials[blockIdx.x] = ((red[0] + red[1]) + (red[2] + red[3]))
                               + ((red[4] + red[5]) + (red[6] + red[7]));
        __threadfence();
        const unsigned int c = atomicAdd(&g_count, 1u);
        is_last = (c == NBLK - 1);
    }
    __syncthreads();

    if (is_last) {
        __threadfence();
        double d = 0.0;
        for (int u = t; u < NBLK; u += TPB) d += (double)g_partials[u];

        __shared__ double rs[TPB];
        rs[t] = d;
        __syncthreads();
#pragma unroll
        for (int o = TPB / 2; o > 0; o >>= 1) {
            if (t < o) rs[t] += rs[t + o];
            __syncthreads();
        }
        if (t == 0) {
            const double INV_4PI = 0.07957747154594767;
            out[0] = (float)(rs[0] * INV_4PI);
            g_count = 0;   // reset for next graph replay
        }
    }
}

extern "C" void kernel_launch(void* const* d_in, const int* in_sizes, int n_in,
                              void* d_out, int out_size) {
    const float* pos = (const float*)d_in[0];   // [8192,3] fp32
    const float* q   = (const float*)d_in[1];   // [8192,4] fp32
    float* out = (float*)d_out;                 // [1] fp32

    bin_hist_kernel<<<NPTS / 256, 256>>>(pos);
    tot_kernel<<<NBINS / 256, 256>>>();
    scan_kernel<<<1, 256>>>();
    colstart_kernel<<<NBINS / 256, 256>>>();
    gather_kernel<<<NPTS / 256, 256>>>(pos, q);
    ewald_pair_kernel<<<NBLK, TPB>>>(out);
}